// round 5
// baseline (speedup 1.0000x reference)
#include <cuda_runtime.h>

typedef unsigned long long ull;

#define NSAMP 4096
#define DIM   256
#define NCLS  6

#define BM 128
#define BN 128
#define BK 16

// ---------------- device scratch (no allocations allowed) ----------------
__device__ float  g_ss[NSAMP];           // ||source_i||^2
__device__ float  g_tt[NSAMP];           // ||target_j||^2
__device__ float  g_colsum[DIM];         // column sums of concat(S,T)
__device__ double g_sqsum;               // sum of all squared norms
__device__ float  g_neg_inv_bw16;        // -1/(bandwidth*16)
__device__ ull    g_min_row[NSAMP];      // per source row: packed (d2,target idx)
__device__ ull    g_min_col[NSAMP];      // per target col: packed (d2,source idx)
__device__ double g_ksum[3];             // SS, TT, ST kernel sums
__device__ double g_clf_sum;
__device__ double g_dis_sum;
__device__ int    g_label64;

// ---------------- init ----------------
__global__ void init_kernel() {
    int i = blockIdx.x * blockDim.x + threadIdx.x;
    if (i < NSAMP) { g_min_row[i] = ~0ull; g_min_col[i] = ~0ull; }
    if (i < DIM)   g_colsum[i] = 0.f;
    if (i < 3)     g_ksum[i] = 0.0;
    if (i == 0)    { g_sqsum = 0.0; g_clf_sum = 0.0; g_dis_sum = 0.0; }
}

// Detect whether labels are serialized as int64 (odd 32-bit words all zero)
// or int32. Safe: we only scan the first 4096 words, valid in both cases.
__global__ void detect_labels(const int* __restrict__ w) {
    __shared__ int any;
    if (threadIdx.x == 0) any = 0;
    __syncthreads();
    for (int i = 1 + 2 * threadIdx.x; i < NSAMP; i += 2 * blockDim.x)
        if (w[i] != 0) any = 1;
    __syncthreads();
    if (threadIdx.x == 0) g_label64 = (any == 0) ? 1 : 0;
}

// ---------------- row norms + total squared sum ----------------
__global__ void row_norms(const float* __restrict__ S, const float* __restrict__ T) {
    int r = blockIdx.x;            // 0..8191
    const float* X = (r < NSAMP) ? (S + (size_t)r * DIM)
                                 : (T + (size_t)(r - NSAMP) * DIM);
    float v = X[threadIdx.x];
    float sq = v * v;
    for (int o = 16; o; o >>= 1) sq += __shfl_down_sync(0xffffffffu, sq, o);
    __shared__ float ws[8];
    if ((threadIdx.x & 31) == 0) ws[threadIdx.x >> 5] = sq;
    __syncthreads();
    if (threadIdx.x == 0) {
        float tot = 0.f;
        #pragma unroll
        for (int k = 0; k < 8; k++) tot += ws[k];
        if (r < NSAMP) g_ss[r] = tot; else g_tt[r - NSAMP] = tot;
        atomicAdd(&g_sqsum, (double)tot);
    }
}

// ---------------- column sums of concat(S,T) ----------------
__global__ void col_sums(const float* __restrict__ S, const float* __restrict__ T) {
    int c  = threadIdx.x;          // 0..255
    int r0 = blockIdx.x * 128;     // 64 blocks * 128 rows = 8192
    float acc = 0.f;
    for (int r = r0; r < r0 + 128; r++) {
        const float* X = (r < NSAMP) ? (S + (size_t)r * DIM)
                                     : (T + (size_t)(r - NSAMP) * DIM);
        acc += X[c];
    }
    atomicAdd(&g_colsum[c], acc);
}

// ---------------- bandwidth: sum(l2) = 2n*sum(sq) - 2*||colsum||^2 ----------------
__global__ void bandwidth_kernel() {
    float cs = g_colsum[threadIdx.x];
    double p = (double)cs * (double)cs;
    for (int o = 16; o; o >>= 1) p += __shfl_down_sync(0xffffffffu, p, o);
    __shared__ double ws[8];
    if ((threadIdx.x & 31) == 0) ws[threadIdx.x >> 5] = p;
    __syncthreads();
    if (threadIdx.x == 0) {
        double ssv = 0.0;
        #pragma unroll
        for (int k = 0; k < 8; k++) ssv += ws[k];
        double n = 2.0 * NSAMP;
        double sumL2 = 2.0 * n * g_sqsum - 2.0 * ssv;
        double b = sumL2 / (n * n - n) / 4.0;   // / KERNEL_MUL^(KERNEL_NUM//2)
        g_neg_inv_bw16 = (float)(-1.0 / (b * 16.0));
    }
}

// ---------------- cross entropy ----------------
__global__ void clf_kernel(const float* __restrict__ sclf, const int* __restrict__ lw) {
    int i = blockIdx.x * blockDim.x + threadIdx.x;
    float loss = 0.f;
    if (i < NSAMP) {
        const float* x = sclf + i * NCLS;
        float m = x[0];
        #pragma unroll
        for (int c = 1; c < NCLS; c++) m = fmaxf(m, x[c]);
        float se = 0.f;
        #pragma unroll
        for (int c = 0; c < NCLS; c++) se += __expf(x[c] - m);
        float lse = m + __logf(se);
        int lab = g_label64 ? lw[2 * i] : lw[i];
        loss = lse - x[lab];
    }
    for (int o = 16; o; o >>= 1) loss += __shfl_down_sync(0xffffffffu, loss, o);
    if ((threadIdx.x & 31) == 0) atomicAdd(&g_clf_sum, (double)loss);
}

// ---------------- fused pairwise-distance GEMM + MMD kernel sum + argmin ----------------
// MODE 0: S x S (symmetric, upper triangle, weight 2 off-diag)
// MODE 1: T x T (same)
// MODE 2: S x T (full; also tracks row/col argmin of clamped d2)
template <int MODE>
__global__ __launch_bounds__(256, 2)
void pair_kernel(const float* __restrict__ A, const float* __restrict__ B) {
    int bi = blockIdx.y, bj = blockIdx.x;
    if (MODE != 2 && bi > bj) return;

    __shared__ __align__(16) float As[BK][BM];
    __shared__ __align__(16) float Bs[BK][BN];

    int tid = threadIdx.x;
    int tx = tid & 15, ty = tid >> 4;
    int rowA0 = bi * BM, rowB0 = bj * BN;

    int lr = tid >> 2;           // 0..63
    int lc = (tid & 3) << 2;     // 0,4,8,12

    const float* pA = A + (size_t)(rowA0 + lr) * DIM + lc;
    const float* pB = B + (size_t)(rowB0 + lr) * DIM + lc;

    float acc[8][8];
    #pragma unroll
    for (int i = 0; i < 8; i++)
        #pragma unroll
        for (int j = 0; j < 8; j++) acc[i][j] = 0.f;

    // prefetch first k-tile into registers
    float4 a0 = *(const float4*)(pA);
    float4 a1 = *(const float4*)(pA + 64 * DIM);
    float4 b0 = *(const float4*)(pB);
    float4 b1 = *(const float4*)(pB + 64 * DIM);

    for (int k0 = 0; k0 < DIM; k0 += BK) {
        // stage current tile into smem (transposed: As[k][m])
        As[lc + 0][lr]      = a0.x; As[lc + 1][lr]      = a0.y;
        As[lc + 2][lr]      = a0.z; As[lc + 3][lr]      = a0.w;
        As[lc + 0][lr + 64] = a1.x; As[lc + 1][lr + 64] = a1.y;
        As[lc + 2][lr + 64] = a1.z; As[lc + 3][lr + 64] = a1.w;
        Bs[lc + 0][lr]      = b0.x; Bs[lc + 1][lr]      = b0.y;
        Bs[lc + 2][lr]      = b0.z; Bs[lc + 3][lr]      = b0.w;
        Bs[lc + 0][lr + 64] = b1.x; Bs[lc + 1][lr + 64] = b1.y;
        Bs[lc + 2][lr + 64] = b1.z; Bs[lc + 3][lr + 64] = b1.w;
        __syncthreads();

        // prefetch next tile while computing
        if (k0 + BK < DIM) {
            a0 = *(const float4*)(pA + k0 + BK);
            a1 = *(const float4*)(pA + 64 * DIM + k0 + BK);
            b0 = *(const float4*)(pB + k0 + BK);
            b1 = *(const float4*)(pB + 64 * DIM + k0 + BK);
        }

        #pragma unroll
        for (int k = 0; k < BK; ++k) {
            float4 x0 = *(const float4*)&As[k][ty * 8];
            float4 x1 = *(const float4*)&As[k][ty * 8 + 4];
            float4 y0 = *(const float4*)&Bs[k][tx * 8];
            float4 y1 = *(const float4*)&Bs[k][tx * 8 + 4];
            float ra[8] = {x0.x, x0.y, x0.z, x0.w, x1.x, x1.y, x1.z, x1.w};
            float rb[8] = {y0.x, y0.y, y0.z, y0.w, y1.x, y1.y, y1.z, y1.w};
            #pragma unroll
            for (int i = 0; i < 8; i++)
                #pragma unroll
                for (int j = 0; j < 8; j++)
                    acc[i][j] = fmaf(ra[i], rb[j], acc[i][j]);
        }
        __syncthreads();
    }

    // ---- epilogue ----
    const float* nA = (MODE == 1) ? g_tt : g_ss;
    const float* nB = (MODE == 0) ? g_ss : g_tt;
    float nib = g_neg_inv_bw16;
    float na[8], nb[8];
    #pragma unroll
    for (int i = 0; i < 8; i++) na[i] = nA[rowA0 + ty * 8 + i];
    #pragma unroll
    for (int j = 0; j < 8; j++) nb[j] = nB[rowB0 + tx * 8 + j];

    float part = 0.f;

    if (MODE == 2) {
        __shared__ ull sRow[BM];
        __shared__ ull sCol[BN];
        for (int t = tid; t < BM; t += 256) sRow[t] = ~0ull;
        for (int t = tid; t < BN; t += 256) sCol[t] = ~0ull;
        __syncthreads();

        ull colbest[8];
        #pragma unroll
        for (int j = 0; j < 8; j++) colbest[j] = ~0ull;

        #pragma unroll
        for (int i = 0; i < 8; i++) {
            ull rowbest = ~0ull;
            unsigned gi = (unsigned)(rowA0 + ty * 8 + i);
            #pragma unroll
            for (int j = 0; j < 8; j++) {
                float d2 = na[i] + nb[j] - 2.f * acc[i][j];
                float e  = __expf(d2 * nib);
                float e2 = e * e, e4 = e2 * e2, e8 = e4 * e4, e16 = e8 * e8;
                part += e + e2 + e4 + e8 + e16;

                float d2c = fmaxf(d2, 0.f);
                unsigned fb = __float_as_uint(d2c);
                ull kr = ((ull)fb << 32) | (unsigned)(rowB0 + tx * 8 + j);
                if (kr < rowbest) rowbest = kr;
                ull kc = ((ull)fb << 32) | gi;
                if (kc < colbest[j]) colbest[j] = kc;
            }
            atomicMin(&sRow[ty * 8 + i], rowbest);
        }
        #pragma unroll
        for (int j = 0; j < 8; j++) atomicMin(&sCol[tx * 8 + j], colbest[j]);
        __syncthreads();
        if (tid < BM)      atomicMin(&g_min_row[rowA0 + tid], sRow[tid]);
        else               atomicMin(&g_min_col[rowB0 + tid - BM], sCol[tid - BM]);
    } else {
        #pragma unroll
        for (int i = 0; i < 8; i++)
            #pragma unroll
            for (int j = 0; j < 8; j++) {
                float d2 = na[i] + nb[j] - 2.f * acc[i][j];
                float e  = __expf(d2 * nib);
                float e2 = e * e, e4 = e2 * e2, e8 = e4 * e4, e16 = e8 * e8;
                part += e + e2 + e4 + e8 + e16;
            }
        if (bi != bj) part *= 2.f;   // account for the mirrored tile
    }

    for (int o = 16; o; o >>= 1) part += __shfl_down_sync(0xffffffffu, part, o);
    if ((tid & 31) == 0) atomicAdd(&g_ksum[MODE], (double)part);
}

// ---------------- distillation losses ----------------
__device__ __forceinline__ float distill_row(const float* te, const float* st) {
    float mt = te[0], ms = st[0];
    #pragma unroll
    for (int c = 1; c < NCLS; c++) { mt = fmaxf(mt, te[c]); ms = fmaxf(ms, st[c]); }
    float set = 0.f, ses = 0.f;
    #pragma unroll
    for (int c = 0; c < NCLS; c++) { set += __expf(te[c] - mt); ses += __expf(st[c] - ms); }
    float lses = ms + __logf(ses);
    float inv = 1.f / set;
    float acc = 0.f;
    #pragma unroll
    for (int c = 0; c < NCLS; c++)
        acc += __expf(te[c] - mt) * inv * (lses - st[c]);
    return acc;
}

__global__ void dis_kernel(const float* __restrict__ sclf, const float* __restrict__ tclf) {
    int i = blockIdx.x * blockDim.x + threadIdx.x;
    float loss = 0.f;
    if (i < NSAMP) {
        int mi  = (int)(g_min_row[i] & 0xffffffffull);  // nearest target of source i
        int mti = (int)(g_min_col[i] & 0xffffffffull);  // nearest source of target i
        loss = distill_row(sclf + i * NCLS, tclf + mi * NCLS)
             + distill_row(sclf + mti * NCLS, tclf + i * NCLS);
    }
    for (int o = 16; o; o >>= 1) loss += __shfl_down_sync(0xffffffffu, loss, o);
    if ((threadIdx.x & 31) == 0) atomicAdd(&g_dis_sum, (double)loss);
}

__global__ void finalize_kernel(float* __restrict__ out) {
    out[0] = (float)(g_clf_sum / (double)NSAMP);
    out[1] = (float)(g_dis_sum / (double)NSAMP);
    out[2] = (float)((g_ksum[0] + g_ksum[1] - 2.0 * g_ksum[2]) /
                     ((double)NSAMP * (double)NSAMP));
}

// ---------------- launch ----------------
extern "C" void kernel_launch(void* const* d_in, const int* in_sizes, int n_in,
                              void* d_out, int out_size) {
    const float* S    = (const float*)d_in[0];
    const float* T    = (const float*)d_in[1];
    const float* sclf = (const float*)d_in[2];
    const float* tclf = (const float*)d_in[3];
    const int*   lab  = (const int*)d_in[4];
    float* out = (float*)d_out;

    init_kernel<<<16, 256>>>();
    detect_labels<<<1, 256>>>(lab);
    row_norms<<<2 * NSAMP, 256>>>(S, T);
    col_sums<<<64, 256>>>(S, T);
    bandwidth_kernel<<<1, 256>>>();
    clf_kernel<<<16, 256>>>(sclf, lab);

    dim3 grid(NSAMP / BN, NSAMP / BM);
    pair_kernel<0><<<grid, 256>>>(S, S);
    pair_kernel<1><<<grid, 256>>>(T, T);
    pair_kernel<2><<<grid, 256>>>(S, T);

    dis_kernel<<<16, 256>>>(sclf, tclf);
    finalize_kernel<<<1, 1>>>(out);
}